// round 3
// baseline (speedup 1.0000x reference)
#include <cuda_runtime.h>
#include <math.h>
#include <stdint.h>

#define N_LEVELS   16
#define HASH_MASK  0x7FFFFu          // 2^19 - 1
#define TABLE_SIZE (1u << 19)

struct HashParams {
    int   res[N_LEVELS];
    float resf[N_LEVELS];
    float rcpf[N_LEVELS];   // RN32(1/res), matching XLA's div->mul rewrite
};

__global__ __launch_bounds__(256)
void hash_encode_kernel(const float* __restrict__ x,
                        const float2* __restrict__ tables,
                        float4* __restrict__ out,
                        int N, HashParams p)
{
    int n = blockIdx.x * blockDim.x + threadIdx.x;
    if (n >= N) return;

    float xv0 = fminf(fmaxf(x[n * 3 + 0], -1.0f), 1.0f);
    float xv1 = fminf(fmaxf(x[n * 3 + 1], -1.0f), 1.0f);
    float xv2 = fminf(fmaxf(x[n * 3 + 2], -1.0f), 1.0f);
    float xv[3] = {xv0, xv1, xv2};

    const unsigned PRIME[3] = {1u, 2654435761u, 805459861u};

    float acc[2 * N_LEVELS];

#pragma unroll
    for (int l = 0; l < N_LEVELS; l++) {
        const int   resi = p.res[l];
        const float resf = p.resf[l];
        const float rcp  = p.rcpf[l];
        const float2* __restrict__ tb = tables + (size_t)l * TABLE_SIZE;

        unsigned term[3][2];
        float    wgt[3][2];

#pragma unroll
        for (int d = 0; d < 3; d++) {
            float c  = xv[d] * resf;          // coords
            float cf = floorf(c);
            float lc = c - cf;                // fractional part
            int   ci = (int)cf;               // in [-res, res]
            wgt[d][0] = 1.0f - lc;
            wgt[d][1] = lc;
#pragma unroll
            for (int b = 0; b < 2; b++) {
                int m = ci + b;               // in [-res, res+1]
                if (m < 0)     m += resi;     // Python-style mod
                if (m >= resi) m -= resi;
                // corners_f = m * (1/res)  — XLA rewrites div-by-constant
                // into multiply by the RN32 reciprocal; replicate exactly.
                float cfr = __fmul_rn((float)m, rcp);
                // q = trunc(RN(cfr + 1) * 131072)  — two separate roundings,
                // intrinsics prevent FMA contraction.
                float t = __fmul_rn(__fadd_rn(cfr, 1.0f), 131072.0f);
                unsigned q = (unsigned)t;
                term[d][b] = q * PRIME[d];    // uint32 wrap keeps low 19 bits
            }
        }

        // 8 corners: issue all gathers, then accumulate
        float2 f[8];
        float  w[8];
#pragma unroll
        for (int k = 0; k < 8; k++) {
            int b0 = (k >> 2) & 1, b1 = (k >> 1) & 1, b2 = k & 1;
            unsigned h = (term[0][b0] + term[1][b1] + term[2][b2]) & HASH_MASK;
            f[k] = __ldg(tb + h);
            w[k] = wgt[0][b0] * wgt[1][b1] * wgt[2][b2];
        }
        float a0 = 0.0f, a1 = 0.0f;
#pragma unroll
        for (int k = 0; k < 8; k++) {
            a0 += w[k] * f[k].x;
            a1 += w[k] * f[k].y;
        }
        acc[2 * l]     = a0;
        acc[2 * l + 1] = a1;
    }

    float4* o = out + (size_t)n * 8;
#pragma unroll
    for (int k = 0; k < 8; k++) {
        o[k] = make_float4(acc[4 * k], acc[4 * k + 1], acc[4 * k + 2], acc[4 * k + 3]);
    }
}

extern "C" void kernel_launch(void* const* d_in, const int* in_sizes, int n_in,
                              void* d_out, int out_size)
{
    const float*  x      = (const float*)d_in[0];
    const float2* tables = (const float2*)d_in[1];
    float4*       out    = (float4*)d_out;

    int N = in_sizes[0] / 3;

    HashParams p;
    for (int i = 0; i < N_LEVELS; i++) {
        double r = 16.0 * pow(32.0, (double)i / 15.0);  // same libm as Python ref
        p.res[i]  = (int)r;
        p.resf[i] = (float)p.res[i];
        p.rcpf[i] = 1.0f / p.resf[i];   // IEEE RN32 reciprocal
    }

    int threads = 256;
    int blocks  = (N + threads - 1) / threads;
    hash_encode_kernel<<<blocks, threads>>>(x, tables, out, N, p);
}

// round 4
// speedup vs baseline: 1.0107x; 1.0107x over previous
#include <cuda_runtime.h>
#include <math.h>
#include <stdint.h>

#define N_LEVELS   16
#define HASH_MASK  0x7FFFFu          // 2^19 - 1
#define TABLE_SIZE (1u << 19)

struct HashParams {
    int   res[N_LEVELS];
    float resf[N_LEVELS];
    float rcpf[N_LEVELS];   // RN32(1/res), matching XLA's div->mul rewrite
};

__global__ __launch_bounds__(256, 6)
void hash_encode_kernel(const float* __restrict__ x,
                        const float2* __restrict__ tables,
                        float4* __restrict__ out,
                        int N, HashParams p)
{
    int n = blockIdx.x * blockDim.x + threadIdx.x;
    if (n >= N) return;

    float xv0 = fminf(fmaxf(x[n * 3 + 0], -1.0f), 1.0f);
    float xv1 = fminf(fmaxf(x[n * 3 + 1], -1.0f), 1.0f);
    float xv2 = fminf(fmaxf(x[n * 3 + 2], -1.0f), 1.0f);
    float xv[3] = {xv0, xv1, xv2};

    const unsigned PRIME[3] = {1u, 2654435761u, 805459861u};

    float4* o = out + (size_t)n * 8;

    // 4 groups of 4 levels: only 8 accumulator floats live at a time,
    // stores issued per group -> regs fit 6 blocks/SM (48 warps).
#pragma unroll
    for (int g = 0; g < 4; g++) {
        float accg[8];

#pragma unroll
        for (int li = 0; li < 4; li++) {
            const int   l    = 4 * g + li;
            const int   resi = p.res[l];
            const float resf = p.resf[l];
            const float rcp  = p.rcpf[l];
            const float2* __restrict__ tb = tables + (size_t)l * TABLE_SIZE;

            unsigned term[3][2];
            float    wgt[3][2];

#pragma unroll
            for (int d = 0; d < 3; d++) {
                float c  = xv[d] * resf;          // coords
                float cf = floorf(c);
                float lc = c - cf;                // fractional part
                int   ci = (int)cf;               // in [-res, res]
                wgt[d][0] = 1.0f - lc;
                wgt[d][1] = lc;
#pragma unroll
                for (int b = 0; b < 2; b++) {
                    int m = ci + b;               // in [-res, res+1]
                    if (m < 0)     m += resi;     // Python-style mod
                    if (m >= resi) m -= resi;
                    // corners_f = m * RN32(1/res)  (XLA div->mul rewrite)
                    float cfr = __fmul_rn((float)m, rcp);
                    // q = trunc(RN(cfr + 1) * 131072), two roundings,
                    // intrinsics block FMA contraction.
                    float t = __fmul_rn(__fadd_rn(cfr, 1.0f), 131072.0f);
                    unsigned q = (unsigned)t;
                    term[d][b] = q * PRIME[d];    // uint32 wrap keeps low 19 bits
                }
            }

            // 8 corners: issue all gathers, then accumulate
            float2 f[8];
            float  w[8];
#pragma unroll
            for (int k = 0; k < 8; k++) {
                int b0 = (k >> 2) & 1, b1 = (k >> 1) & 1, b2 = k & 1;
                unsigned h = (term[0][b0] + term[1][b1] + term[2][b2]) & HASH_MASK;
                f[k] = __ldg(tb + h);
                w[k] = wgt[0][b0] * wgt[1][b1] * wgt[2][b2];
            }
            float a0 = 0.0f, a1 = 0.0f;
#pragma unroll
            for (int k = 0; k < 8; k++) {
                a0 += w[k] * f[k].x;
                a1 += w[k] * f[k].y;
            }
            accg[2 * li]     = a0;
            accg[2 * li + 1] = a1;
        }

        o[2 * g]     = make_float4(accg[0], accg[1], accg[2], accg[3]);
        o[2 * g + 1] = make_float4(accg[4], accg[5], accg[6], accg[7]);
    }
}

extern "C" void kernel_launch(void* const* d_in, const int* in_sizes, int n_in,
                              void* d_out, int out_size)
{
    const float*  x      = (const float*)d_in[0];
    const float2* tables = (const float2*)d_in[1];
    float4*       out    = (float4*)d_out;

    int N = in_sizes[0] / 3;

    HashParams p;
    for (int i = 0; i < N_LEVELS; i++) {
        double r = 16.0 * pow(32.0, (double)i / 15.0);  // same libm as Python ref
        p.res[i]  = (int)r;
        p.resf[i] = (float)p.res[i];
        p.rcpf[i] = 1.0f / p.resf[i];   // IEEE RN32 reciprocal
    }

    int threads = 256;
    int blocks  = (N + threads - 1) / threads;
    hash_encode_kernel<<<blocks, threads>>>(x, tables, out, N, p);
}